// round 2
// baseline (speedup 1.0000x reference)
#include <cuda_runtime.h>
#include <math.h>

#define BB    16
#define NN    512
#define MM    1024
#define CC    8
#define COUT  64
#define SPLIT 4
#define MPB   32              // m-values per block
#define TPB   (MPB * SPLIT)   // 128 threads

__device__ __forceinline__ float ex2f(float x) {
    float y;
    asm("ex2.approx.ftz.f32 %0, %1;" : "=f"(y) : "f"(x));
    return y;
}
__device__ __forceinline__ unsigned long long pack2(float lo, float hi) {
    unsigned long long r;
    asm("mov.b64 %0, {%1, %2};" : "=l"(r) : "f"(lo), "f"(hi));
    return r;
}
__device__ __forceinline__ void unpack2(unsigned long long v, float& lo, float& hi) {
    asm("mov.b64 {%0, %1}, %2;" : "=f"(lo), "=f"(hi) : "l"(v));
}
__device__ __forceinline__ void ffma2(unsigned long long& d, unsigned long long a, unsigned long long b) {
    asm("fma.rn.f32x2 %0, %1, %2, %0;" : "+l"(d) : "l"(a), "l"(b));
}

__global__ __launch_bounds__(TPB)
void convdeepset_kernel(const float* __restrict__ ci,    // (B,N,1)
                        const float* __restrict__ co,    // (B,N,7)
                        const float* __restrict__ ti,    // (B,M,1)
                        const float* __restrict__ sigma, // (8,)
                        const float* __restrict__ W,     // (64,8)
                        const float* __restrict__ bias,  // (64,)
                        float* __restrict__ out)         // (B,M,64)
{
    __shared__ float2      s_ab[NN];        // uniform: (k2*x^2, -2*k2*x); else (x, 0)
    __shared__ ulonglong2  s_cx[NN * 2];    // packed f32x2 pairs: (1,c0)(c1,c2) | (c3,c4)(c5,c6)
    __shared__ float       s_Wt[CC][COUT];  // W transposed [c][o]
    __shared__ float       s_bias[COUT];

    const int tid = threadIdx.x;
    const int s   = tid & (SPLIT - 1);   // n-split lane
    const int ml  = tid >> 2;            // local m
    const int blk = blockIdx.x;
    const int b   = blk >> 5;            // MM/MPB = 32 tiles per batch
    const int mt  = blk & 31;
    const int m   = mt * MPB + ml;

    // stage W^T + bias
    for (int i = tid; i < CC * COUT; i += TPB) {
        int o = i / CC, c = i % CC;
        s_Wt[c][o] = W[i];
    }
    if (tid < COUT) s_bias[tid] = bias[tid];

    // uniform-sigma detection (per-thread, all hit same cacheline)
    const float LOG2E = 1.4426950408889634f;
    float sg0 = sigma[0];
    bool uni = true;
    #pragma unroll
    for (int c = 1; c < CC; c++) uni &= (sigma[c] == sg0);
    const float k2u = -0.5f * LOG2E * expf(-2.0f * sg0);

    // stage context: precompute exponent coefficients + packed channels
    const float* cib = ci + (size_t)b * NN;
    const float* cob = co + (size_t)b * NN * 7;
    for (int i = tid; i < NN; i += TPB) {
        float x = cib[i];
        float2 ab;
        if (uni) { ab.x = k2u * x * x; ab.y = -2.0f * k2u * x; }
        else     { ab.x = x;           ab.y = 0.0f; }
        s_ab[i] = ab;
        const float* r = cob + i * 7;
        float c0 = r[0], c1 = r[1], c2 = r[2], c3 = r[3], c4 = r[4], c5 = r[5], c6 = r[6];
        s_cx[2 * i]     = make_ulonglong2(pack2(1.0f, c0), pack2(c1, c2));
        s_cx[2 * i + 1] = make_ulonglong2(pack2(c3, c4), pack2(c5, c6));
    }
    __syncthreads();

    const float t = ti[(size_t)b * MM + m];

    float f[CC];
    if (uni) {
        // fast path: w' = exp2(a_n + b_n*t); exp2(k2*t^2) factor reapplied to density only
        unsigned long long a0 = 0ull, a1 = 0ull, a2 = 0ull, a3 = 0ull; // bits(0,0) = (0.f,0.f)
        #pragma unroll 4
        for (int n = s; n < NN; n += SPLIT) {
            float2 ab = s_ab[n];
            float w = ex2f(fmaf(ab.y, t, ab.x));
            unsigned long long w2 = pack2(w, w);
            ulonglong2 p = s_cx[2 * n];
            ulonglong2 q = s_cx[2 * n + 1];
            ffma2(a0, w2, p.x);
            ffma2(a1, w2, p.y);
            ffma2(a2, w2, q.x);
            ffma2(a3, w2, q.y);
        }
        unpack2(a0, f[0], f[1]);
        unpack2(a1, f[2], f[3]);
        unpack2(a2, f[4], f[5]);
        unpack2(a3, f[6], f[7]);
    } else {
        // general path: per-channel scales
        float k2[CC];
        #pragma unroll
        for (int c = 0; c < CC; c++) k2[c] = -0.5f * LOG2E * expf(-2.0f * sigma[c]);
        #pragma unroll
        for (int c = 0; c < CC; c++) f[c] = 0.0f;
        for (int n = s; n < NN; n += SPLIT) {
            float x = s_ab[n].x;
            float diff = x - t;
            float d = diff * diff;
            const float* cf = (const float*)&s_cx[2 * n];
            #pragma unroll
            for (int c = 0; c < CC; c++) f[c] += ex2f(d * k2[c]) * cf[c];
        }
    }

    // butterfly reduce over the 4 split lanes (same m within each 4-lane group)
    #pragma unroll
    for (int c = 0; c < CC; c++) {
        f[c] += __shfl_xor_sync(0xffffffffu, f[c], 1);
        f[c] += __shfl_xor_sync(0xffffffffu, f[c], 2);
    }

    // normalize + density correction
    float v[CC];
    float inv = 1.0f / (f[0] + 1e-8f);
    float dcorr = uni ? ex2f(k2u * t * t) : 1.0f;
    v[0] = f[0] * dcorr;
    #pragma unroll
    for (int c = 1; c < CC; c++) v[c] = f[c] * inv;

    // fused (8 -> 64) GEMM + bias; each split lane emits 16 of the 64 outputs
    float4* outp = (float4*)(out + ((size_t)(b * MM + m)) * COUT);
    #pragma unroll
    for (int j = 0; j < 4; j++) {
        int o4 = s * 4 + j;
        float4 r = *(const float4*)&s_bias[o4 * 4];
        #pragma unroll
        for (int c = 0; c < CC; c++) {
            float4 w4 = *(const float4*)&s_Wt[c][o4 * 4];
            r.x = fmaf(v[c], w4.x, r.x);
            r.y = fmaf(v[c], w4.y, r.y);
            r.z = fmaf(v[c], w4.z, r.z);
            r.w = fmaf(v[c], w4.w, r.w);
        }
        outp[o4] = r;
    }
}

extern "C" void kernel_launch(void* const* d_in, const int* in_sizes, int n_in,
                              void* d_out, int out_size) {
    const float* ci    = (const float*)d_in[0];
    const float* co    = (const float*)d_in[1];
    const float* ti    = (const float*)d_in[2];
    const float* sigma = (const float*)d_in[3];
    const float* W     = (const float*)d_in[4];
    const float* bias  = (const float*)d_in[5];
    float* out = (float*)d_out;

    dim3 grid(BB * (MM / MPB));   // 16 * 32 = 512 blocks
    dim3 block(TPB);              // 128 threads
    convdeepset_kernel<<<grid, block>>>(ci, co, ti, sigma, W, bias, out);
}

// round 3
// speedup vs baseline: 1.4168x; 1.4168x over previous
#include <cuda_runtime.h>
#include <math.h>

#define BB    16
#define NN    512
#define MM    1024
#define CC    8
#define COUT  64
#define NWARP 8               // n-split across warps
#define MPB   32              // m-values per block (= lanes per warp)
#define TPB   (MPB * NWARP)   // 256 threads
#define NPW   (NN / NWARP)    // 64 n per warp

__device__ __forceinline__ float ex2f(float x) {
    float y;
    asm("ex2.approx.ftz.f32 %0, %1;" : "=f"(y) : "f"(x));
    return y;
}
__device__ __forceinline__ unsigned long long pack2(float lo, float hi) {
    unsigned long long r;
    asm("mov.b64 %0, {%1, %2};" : "=l"(r) : "f"(lo), "f"(hi));
    return r;
}
__device__ __forceinline__ void unpack2(unsigned long long v, float& lo, float& hi) {
    asm("mov.b64 {%0, %1}, %2;" : "=f"(lo), "=f"(hi) : "l"(v));
}
__device__ __forceinline__ void ffma2(unsigned long long& d, unsigned long long a, unsigned long long b) {
    asm("fma.rn.f32x2 %0, %1, %2, %0;" : "+l"(d) : "l"(a), "l"(b));
}

__global__ __launch_bounds__(TPB)
void convdeepset_kernel(const float* __restrict__ ci,    // (B,N,1)
                        const float* __restrict__ co,    // (B,N,7)
                        const float* __restrict__ ti,    // (B,M,1)
                        const float* __restrict__ sigma, // (8,)
                        const float* __restrict__ W,     // (64,8)
                        const float* __restrict__ bias,  // (64,)
                        float* __restrict__ out)         // (B,M,64)
{
    __shared__ float2      s_ab[NN];               // uniform: (k2*x^2, -2*k2*x); else (x, unused)
    __shared__ ulonglong2  s_cx[NN * 2];           // packed f32x2: (1,c0)(c1,c2) | (c3,c4)(c5,c6)
    __shared__ float       s_part[NWARP][CC][MPB]; // per-warp partial sums
    __shared__ float       s_v[CC][MPB];           // normalized features
    __shared__ float       s_dens[MPB];            // raw density partial (pre-g)
    __shared__ float       s_Wt[CC][COUT];         // W transposed [c][o]
    __shared__ float       s_bias[COUT];

    const int tid  = threadIdx.x;
    const int w    = tid >> 5;          // warp id = n-slice
    const int lane = tid & 31;          // lane = local m
    const int blk  = blockIdx.x;
    const int b    = blk >> 5;          // 32 m-tiles per batch
    const int mt   = blk & 31;
    const int m    = mt * MPB + lane;   // this warp's m for 'lane'

    // stage W^T + bias
    for (int i = tid; i < CC * COUT; i += TPB) {
        int o = i / CC, c = i % CC;
        s_Wt[c][o] = W[i];
    }
    if (tid < COUT) s_bias[tid] = bias[tid];

    // uniform-sigma detection
    const float LOG2E = 1.4426950408889634f;
    float sg0 = sigma[0];
    bool uni = true;
    #pragma unroll
    for (int c = 1; c < CC; c++) uni &= (sigma[c] == sg0);
    const float k2u = -0.5f * LOG2E * expf(-2.0f * sg0);

    // stage context rows (2 rows per thread)
    const float* cib = ci + (size_t)b * NN;
    const float* cob = co + (size_t)b * NN * 7;
    for (int i = tid; i < NN; i += TPB) {
        float x = cib[i];
        float2 ab;
        if (uni) { ab.x = k2u * x * x; ab.y = -2.0f * k2u * x; }
        else     { ab.x = x;           ab.y = 0.0f; }
        s_ab[i] = ab;
        const float* r = cob + i * 7;
        s_cx[2 * i]     = make_ulonglong2(pack2(1.0f, r[0]), pack2(r[1], r[2]));
        s_cx[2 * i + 1] = make_ulonglong2(pack2(r[3], r[4]), pack2(r[5], r[6]));
    }
    __syncthreads();

    const float t = ti[(size_t)b * MM + m];

    // ---- main loop: each warp sums its 64-n slice; all lanes read same n (broadcast LDS) ----
    float f[CC];
    const int n0 = w * NPW;
    if (uni) {
        unsigned long long a0 = 0ull, a1 = 0ull, a2 = 0ull, a3 = 0ull;
        #pragma unroll 4
        for (int i = 0; i < NPW; i++) {
            int n = n0 + i;
            float2 ab = s_ab[n];
            float wt = ex2f(fmaf(ab.y, t, ab.x));     // exp2(k2(x-t)^2 - k2 t^2)
            unsigned long long w2 = pack2(wt, wt);
            ulonglong2 p = s_cx[2 * n];
            ulonglong2 q = s_cx[2 * n + 1];
            ffma2(a0, w2, p.x);
            ffma2(a1, w2, p.y);
            ffma2(a2, w2, q.x);
            ffma2(a3, w2, q.y);
        }
        unpack2(a0, f[0], f[1]);
        unpack2(a1, f[2], f[3]);
        unpack2(a2, f[4], f[5]);
        unpack2(a3, f[6], f[7]);
    } else {
        float k2[CC];
        #pragma unroll
        for (int c = 0; c < CC; c++) k2[c] = -0.5f * LOG2E * expf(-2.0f * sigma[c]);
        #pragma unroll
        for (int c = 0; c < CC; c++) f[c] = 0.0f;
        for (int i = 0; i < NPW; i++) {
            int n = n0 + i;
            float x = s_ab[n].x;
            float diff = x - t;
            float d = diff * diff;
            const float* cf = (const float*)&s_cx[2 * n];
            #pragma unroll
            for (int c = 0; c < CC; c++) f[c] += ex2f(d * k2[c]) * cf[c];
        }
    }

    // write per-warp partials
    #pragma unroll
    for (int c = 0; c < CC; c++) s_part[w][c][lane] = f[c];
    __syncthreads();

    // ---- stage 2: reduce 8 warps; one (c,m) pair per thread ----
    {
        const int c  = tid >> 5;        // 0..7
        const int mm = tid & 31;
        float acc = 0.0f;
        #pragma unroll
        for (int ww = 0; ww < NWARP; ww++) acc += s_part[ww][c][mm];
        if (c == 0) s_dens[mm] = acc;
        __syncthreads();

        float tm = ti[(size_t)b * MM + mt * MPB + mm];
        float g  = uni ? ex2f(k2u * tm * tm) : 1.0f;   // undo dropped exp2(k2 t^2)
        float d0 = s_dens[mm] * g;                      // true density
        float inv = g / (d0 + 1e-8f);
        s_v[c][mm] = (c == 0) ? d0 : acc * inv;
        __syncthreads();
    }

    // ---- stage 3: (8 -> 64) GEMM + bias; thread = (m = tid>>3, og = tid&7), 8 outputs ----
    {
        const int mm = tid >> 3;
        const int og = tid & 7;
        float v[CC];
        #pragma unroll
        for (int c = 0; c < CC; c++) v[c] = s_v[c][mm];

        float4 r0 = *(const float4*)&s_bias[og * 8];
        float4 r1 = *(const float4*)&s_bias[og * 8 + 4];
        #pragma unroll
        for (int c = 0; c < CC; c++) {
            float4 w0 = *(const float4*)&s_Wt[c][og * 8];
            float4 w1 = *(const float4*)&s_Wt[c][og * 8 + 4];
            r0.x = fmaf(v[c], w0.x, r0.x);
            r0.y = fmaf(v[c], w0.y, r0.y);
            r0.z = fmaf(v[c], w0.z, r0.z);
            r0.w = fmaf(v[c], w0.w, r0.w);
            r1.x = fmaf(v[c], w1.x, r1.x);
            r1.y = fmaf(v[c], w1.y, r1.y);
            r1.z = fmaf(v[c], w1.z, r1.z);
            r1.w = fmaf(v[c], w1.w, r1.w);
        }
        float4* outp = (float4*)(out + ((size_t)(b * MM + mt * MPB + mm)) * COUT + og * 8);
        outp[0] = r0;
        outp[1] = r1;
    }
}

extern "C" void kernel_launch(void* const* d_in, const int* in_sizes, int n_in,
                              void* d_out, int out_size) {
    const float* ci    = (const float*)d_in[0];
    const float* co    = (const float*)d_in[1];
    const float* ti    = (const float*)d_in[2];
    const float* sigma = (const float*)d_in[3];
    const float* W     = (const float*)d_in[4];
    const float* bias  = (const float*)d_in[5];
    float* out = (float*)d_out;

    dim3 grid(BB * (MM / MPB));   // 512 blocks
    dim3 block(TPB);              // 256 threads (8 warps)
    convdeepset_kernel<<<grid, block>>>(ci, co, ti, sigma, W, bias, out);
}

// round 4
// speedup vs baseline: 1.5185x; 1.0718x over previous
#include <cuda_runtime.h>
#include <math.h>

#define BB    16
#define NN    512
#define MM    1024
#define CC    8
#define COUT  64
#define NWARP 8               // warps per block, each owns an n-slice
#define NPW   (NN / NWARP)    // 64 n per warp
#define MPB   64              // m-values per block (2 per lane)
#define TPB   (32 * NWARP)    // 256 threads

__device__ __forceinline__ float ex2f(float x) {
    float y;
    asm("ex2.approx.ftz.f32 %0, %1;" : "=f"(y) : "f"(x));
    return y;
}
__device__ __forceinline__ unsigned long long pack2(float lo, float hi) {
    unsigned long long r;
    asm("mov.b64 %0, {%1, %2};" : "=l"(r) : "f"(lo), "f"(hi));
    return r;
}
__device__ __forceinline__ void unpack2(unsigned long long v, float& lo, float& hi) {
    asm("mov.b64 {%0, %1}, %2;" : "=f"(lo), "=f"(hi) : "l"(v));
}
__device__ __forceinline__ void ffma2(unsigned long long& d, unsigned long long a, unsigned long long b) {
    asm("fma.rn.f32x2 %0, %1, %2, %0;" : "+l"(d) : "l"(a), "l"(b));
}

__global__ __launch_bounds__(TPB)
void convdeepset_kernel(const float* __restrict__ ci,    // (B,N,1)
                        const float* __restrict__ co,    // (B,N,7)
                        const float* __restrict__ ti,    // (B,M,1)
                        const float* __restrict__ sigma, // (8,)
                        const float* __restrict__ W,     // (64,8)
                        const float* __restrict__ bias,  // (64,)
                        float* __restrict__ out)         // (B,M,64)
{
    __shared__ float4      s_ab2[NN / 2];            // (a0,b0,a1,b1) per n-pair; general: (x0,0,x1,0)
    __shared__ ulonglong2  s_cx[NN * 2];             // packed f32x2: (1,c0)(c1,c2) | (c3,c4)(c5,c6)
    __shared__ float       s_part[NWARP][CC][MPB];   // per-warp partials (16KB)
    __shared__ float       s_v[CC][MPB];             // normalized features
    __shared__ float       s_dens[MPB];
    __shared__ float       s_Wt[CC][COUT];
    __shared__ float       s_bias[COUT];

    const int tid  = threadIdx.x;
    const int w    = tid >> 5;
    const int lane = tid & 31;
    const int blk  = blockIdx.x;
    const int b    = blk >> 4;          // 16 m-tiles (of 64) per batch
    const int mt   = blk & 15;
    const int mbase = mt * MPB;

    // stage W^T + bias
    for (int i = tid; i < CC * COUT; i += TPB) {
        int o = i / CC, c = i % CC;
        s_Wt[c][o] = W[i];
    }
    if (tid < COUT) s_bias[tid] = bias[tid];

    // uniform-sigma detection
    const float LOG2E = 1.4426950408889634f;
    float sg0 = sigma[0];
    bool uni = true;
    #pragma unroll
    for (int c = 1; c < CC; c++) uni &= (sigma[c] == sg0);
    const float k2u = -0.5f * LOG2E * expf(-2.0f * sg0);

    // stage context rows (2 per thread)
    const float* cib = ci + (size_t)b * NN;
    const float* cob = co + (size_t)b * NN * 7;
    float2* s_abf2 = (float2*)s_ab2;
    for (int i = tid; i < NN; i += TPB) {
        float x = cib[i];
        float2 ab;
        if (uni) { ab.x = k2u * x * x; ab.y = -2.0f * k2u * x; }
        else     { ab.x = x;           ab.y = 0.0f; }
        s_abf2[i] = ab;
        const float* r = cob + i * 7;
        s_cx[2 * i]     = make_ulonglong2(pack2(1.0f, r[0]), pack2(r[1], r[2]));
        s_cx[2 * i + 1] = make_ulonglong2(pack2(r[3], r[4]), pack2(r[5], r[6]));
    }
    __syncthreads();

    const float t0 = ti[(size_t)b * MM + mbase + lane];
    const float t1 = ti[(size_t)b * MM + mbase + lane + 32];

    const int n0 = w * NPW;
    float f0[CC], f1[CC];

    if (uni) {
        unsigned long long x0 = 0ull, x1 = 0ull, x2 = 0ull, x3 = 0ull;  // m0 accum
        unsigned long long y0 = 0ull, y1 = 0ull, y2 = 0ull, y3 = 0ull;  // m1 accum
        #pragma unroll 4
        for (int i = 0; i < NPW / 2; i++) {
            const int np = (n0 >> 1) + i;      // n-pair index
            const int n  = n0 + 2 * i;
            float4 ab = s_ab2[np];
            // 4 independent exponentials: {n, n+1} x {m0, m1}
            float wa0 = ex2f(fmaf(ab.y, t0, ab.x));
            float wb0 = ex2f(fmaf(ab.w, t0, ab.z));
            float wa1 = ex2f(fmaf(ab.y, t1, ab.x));
            float wb1 = ex2f(fmaf(ab.w, t1, ab.z));
            ulonglong2 pa = s_cx[2 * n];
            ulonglong2 qa = s_cx[2 * n + 1];
            ulonglong2 pb = s_cx[2 * n + 2];
            ulonglong2 qb = s_cx[2 * n + 3];
            unsigned long long wa0p = pack2(wa0, wa0);
            unsigned long long wb0p = pack2(wb0, wb0);
            unsigned long long wa1p = pack2(wa1, wa1);
            unsigned long long wb1p = pack2(wb1, wb1);
            ffma2(x0, wa0p, pa.x); ffma2(x1, wa0p, pa.y);
            ffma2(x2, wa0p, qa.x); ffma2(x3, wa0p, qa.y);
            ffma2(x0, wb0p, pb.x); ffma2(x1, wb0p, pb.y);
            ffma2(x2, wb0p, qb.x); ffma2(x3, wb0p, qb.y);
            ffma2(y0, wa1p, pa.x); ffma2(y1, wa1p, pa.y);
            ffma2(y2, wa1p, qa.x); ffma2(y3, wa1p, qa.y);
            ffma2(y0, wb1p, pb.x); ffma2(y1, wb1p, pb.y);
            ffma2(y2, wb1p, qb.x); ffma2(y3, wb1p, qb.y);
        }
        unpack2(x0, f0[0], f0[1]); unpack2(x1, f0[2], f0[3]);
        unpack2(x2, f0[4], f0[5]); unpack2(x3, f0[6], f0[7]);
        unpack2(y0, f1[0], f1[1]); unpack2(y1, f1[2], f1[3]);
        unpack2(y2, f1[4], f1[5]); unpack2(y3, f1[6], f1[7]);
    } else {
        float k2[CC];
        #pragma unroll
        for (int c = 0; c < CC; c++) k2[c] = -0.5f * LOG2E * expf(-2.0f * sigma[c]);
        #pragma unroll
        for (int c = 0; c < CC; c++) { f0[c] = 0.0f; f1[c] = 0.0f; }
        for (int i = 0; i < NPW; i++) {
            int n = n0 + i;
            float x = s_abf2[n].x;
            float d0 = (x - t0) * (x - t0);
            float d1 = (x - t1) * (x - t1);
            const float* cf = (const float*)&s_cx[2 * n];
            #pragma unroll
            for (int c = 0; c < CC; c++) {
                f0[c] += ex2f(d0 * k2[c]) * cf[c];
                f1[c] += ex2f(d1 * k2[c]) * cf[c];
            }
        }
    }

    #pragma unroll
    for (int c = 0; c < CC; c++) {
        s_part[w][c][lane]      = f0[c];
        s_part[w][c][lane + 32] = f1[c];
    }
    __syncthreads();

    // ---- stage 2: reduce 8 warps; thread handles (c, mm) and (c, mm+32) ----
    {
        const int c   = tid >> 5;
        const int mm0 = tid & 31;
        float acc0 = 0.0f, acc1 = 0.0f;
        #pragma unroll
        for (int ww = 0; ww < NWARP; ww++) {
            acc0 += s_part[ww][c][mm0];
            acc1 += s_part[ww][c][mm0 + 32];
        }
        if (c == 0) { s_dens[mm0] = acc0; s_dens[mm0 + 32] = acc1; }
        __syncthreads();

        float ta = ti[(size_t)b * MM + mbase + mm0];
        float tb = ti[(size_t)b * MM + mbase + mm0 + 32];
        float ga = uni ? ex2f(k2u * ta * ta) : 1.0f;
        float gb = uni ? ex2f(k2u * tb * tb) : 1.0f;
        float da = s_dens[mm0] * ga;             // true density
        float db = s_dens[mm0 + 32] * gb;
        float inva = ga / (da + 1e-8f);
        float invb = gb / (db + 1e-8f);
        s_v[c][mm0]      = (c == 0) ? da : acc0 * inva;
        s_v[c][mm0 + 32] = (c == 0) ? db : acc1 * invb;
        __syncthreads();
    }

    // ---- stage 3: (8 -> 64) GEMM + bias; thread = (mm = tid>>2, og = tid&3), 16 outputs ----
    {
        const int mm = tid >> 2;
        const int og = tid & 3;
        float v[CC];
        #pragma unroll
        for (int c = 0; c < CC; c++) v[c] = s_v[c][mm];

        float4* outp = (float4*)(out + ((size_t)(b * MM + mbase + mm)) * COUT + og * 16);
        #pragma unroll
        for (int j = 0; j < 4; j++) {
            int o4 = og * 4 + j;
            float4 r = *(const float4*)&s_bias[o4 * 4];
            #pragma unroll
            for (int c = 0; c < CC; c++) {
                float4 w4 = *(const float4*)&s_Wt[c][o4 * 4];
                r.x = fmaf(v[c], w4.x, r.x);
                r.y = fmaf(v[c], w4.y, r.y);
                r.z = fmaf(v[c], w4.z, r.z);
                r.w = fmaf(v[c], w4.w, r.w);
            }
            outp[j] = r;
        }
    }
}

extern "C" void kernel_launch(void* const* d_in, const int* in_sizes, int n_in,
                              void* d_out, int out_size) {
    const float* ci    = (const float*)d_in[0];
    const float* co    = (const float*)d_in[1];
    const float* ti    = (const float*)d_in[2];
    const float* sigma = (const float*)d_in[3];
    const float* W     = (const float*)d_in[4];
    const float* bias  = (const float*)d_in[5];
    float* out = (float*)d_out;

    dim3 grid(BB * (MM / MPB));   // 16 * 16 = 256 blocks
    dim3 block(TPB);              // 256 threads (8 warps)
    convdeepset_kernel<<<grid, block>>>(ci, co, ti, sigma, W, bias, out);
}

// round 5
// speedup vs baseline: 1.6441x; 1.0827x over previous
#include <cuda_runtime.h>
#include <math.h>

#define BB    16
#define NN    512
#define MM    1024
#define CC    8
#define COUT  64
#define NWARP 16              // warps per block, each owns an n-slice
#define NPW   (NN / NWARP)    // 32 n per warp
#define MPB   64              // m-values per block (2 per lane)
#define TPB   (32 * NWARP)    // 512 threads

__device__ __forceinline__ float ex2f(float x) {
    float y;
    asm("ex2.approx.ftz.f32 %0, %1;" : "=f"(y) : "f"(x));
    return y;
}
__device__ __forceinline__ unsigned long long pack2(float lo, float hi) {
    unsigned long long r;
    asm("mov.b64 %0, {%1, %2};" : "=l"(r) : "f"(lo), "f"(hi));
    return r;
}
__device__ __forceinline__ void unpack2(unsigned long long v, float& lo, float& hi) {
    asm("mov.b64 {%0, %1}, %2;" : "=f"(lo), "=f"(hi) : "l"(v));
}
__device__ __forceinline__ void ffma2(unsigned long long& d, unsigned long long a, unsigned long long b) {
    asm("fma.rn.f32x2 %0, %1, %2, %0;" : "+l"(d) : "l"(a), "l"(b));
}

__global__ __launch_bounds__(TPB)
void convdeepset_kernel(const float* __restrict__ ci,    // (B,N,1)
                        const float* __restrict__ co,    // (B,N,7)
                        const float* __restrict__ ti,    // (B,M,1)
                        const float* __restrict__ sigma, // (8,)
                        const float* __restrict__ W,     // (64,8)
                        const float* __restrict__ bias,  // (64,)
                        float* __restrict__ out)         // (B,M,64)
{
    __shared__ float4      s_ab2[NN / 2];            // (a0,b0,a1,b1) per n-pair
    __shared__ ulonglong2  s_cx[NN * 2];             // packed f32x2: (1,c0)(c1,c2) | (c3,c4)(c5,c6)
    __shared__ float       s_part[NWARP][CC][MPB];   // per-warp partials (32KB)
    __shared__ float       s_v[CC][MPB];
    __shared__ float       s_dens[MPB];
    __shared__ float       s_Wt[CC][COUT];
    __shared__ float       s_bias[COUT];

    const int tid  = threadIdx.x;
    const int w    = tid >> 5;
    const int lane = tid & 31;
    const int blk  = blockIdx.x;
    const int b    = blk >> 4;          // 16 m-tiles (of 64) per batch
    const int mt   = blk & 15;
    const int mbase = mt * MPB;

    // stage W^T + bias
    if (tid < CC * COUT) {
        int o = tid / CC, c = tid % CC;
        s_Wt[c][o] = W[tid];
    }
    if (tid < COUT) s_bias[tid] = bias[tid];

    // uniform-sigma detection
    const float LOG2E = 1.4426950408889634f;
    float sg0 = sigma[0];
    bool uni = true;
    #pragma unroll
    for (int c = 1; c < CC; c++) uni &= (sigma[c] == sg0);
    const float k2u = -0.5f * LOG2E * expf(-2.0f * sg0);

    // stage context rows (1 per thread)
    const float* cib = ci + (size_t)b * NN;
    const float* cob = co + (size_t)b * NN * 7;
    float2* s_abf2 = (float2*)s_ab2;
    {
        int i = tid;
        float x = cib[i];
        float2 ab;
        if (uni) { ab.x = k2u * x * x; ab.y = -2.0f * k2u * x; }
        else     { ab.x = x;           ab.y = 0.0f; }
        s_abf2[i] = ab;
        const float* r = cob + i * 7;
        s_cx[2 * i]     = make_ulonglong2(pack2(1.0f, r[0]), pack2(r[1], r[2]));
        s_cx[2 * i + 1] = make_ulonglong2(pack2(r[3], r[4]), pack2(r[5], r[6]));
    }
    __syncthreads();

    const float t0 = ti[(size_t)b * MM + mbase + lane];
    const float t1 = ti[(size_t)b * MM + mbase + lane + 32];

    const int n0 = w * NPW;
    float f0[CC], f1[CC];

    if (uni) {
        unsigned long long x0 = 0ull, x1 = 0ull, x2 = 0ull, x3 = 0ull;  // m0 accum
        unsigned long long y0 = 0ull, y1 = 0ull, y2 = 0ull, y3 = 0ull;  // m1 accum
        #pragma unroll 4
        for (int i = 0; i < NPW / 2; i++) {
            const int np = (n0 >> 1) + i;
            const int n  = n0 + 2 * i;
            float4 ab = s_ab2[np];
            float wa0 = ex2f(fmaf(ab.y, t0, ab.x));
            float wb0 = ex2f(fmaf(ab.w, t0, ab.z));
            float wa1 = ex2f(fmaf(ab.y, t1, ab.x));
            float wb1 = ex2f(fmaf(ab.w, t1, ab.z));
            ulonglong2 pa = s_cx[2 * n];
            ulonglong2 qa = s_cx[2 * n + 1];
            ulonglong2 pb = s_cx[2 * n + 2];
            ulonglong2 qb = s_cx[2 * n + 3];
            unsigned long long wa0p = pack2(wa0, wa0);
            unsigned long long wb0p = pack2(wb0, wb0);
            unsigned long long wa1p = pack2(wa1, wa1);
            unsigned long long wb1p = pack2(wb1, wb1);
            ffma2(x0, wa0p, pa.x); ffma2(x1, wa0p, pa.y);
            ffma2(x2, wa0p, qa.x); ffma2(x3, wa0p, qa.y);
            ffma2(x0, wb0p, pb.x); ffma2(x1, wb0p, pb.y);
            ffma2(x2, wb0p, qb.x); ffma2(x3, wb0p, qb.y);
            ffma2(y0, wa1p, pa.x); ffma2(y1, wa1p, pa.y);
            ffma2(y2, wa1p, qa.x); ffma2(y3, wa1p, qa.y);
            ffma2(y0, wb1p, pb.x); ffma2(y1, wb1p, pb.y);
            ffma2(y2, wb1p, qb.x); ffma2(y3, wb1p, qb.y);
        }
        unpack2(x0, f0[0], f0[1]); unpack2(x1, f0[2], f0[3]);
        unpack2(x2, f0[4], f0[5]); unpack2(x3, f0[6], f0[7]);
        unpack2(y0, f1[0], f1[1]); unpack2(y1, f1[2], f1[3]);
        unpack2(y2, f1[4], f1[5]); unpack2(y3, f1[6], f1[7]);
    } else {
        float k2[CC];
        #pragma unroll
        for (int c = 0; c < CC; c++) k2[c] = -0.5f * LOG2E * expf(-2.0f * sigma[c]);
        #pragma unroll
        for (int c = 0; c < CC; c++) { f0[c] = 0.0f; f1[c] = 0.0f; }
        for (int i = 0; i < NPW; i++) {
            int n = n0 + i;
            float x = s_abf2[n].x;
            float d0 = (x - t0) * (x - t0);
            float d1 = (x - t1) * (x - t1);
            const float* cf = (const float*)&s_cx[2 * n];
            #pragma unroll
            for (int c = 0; c < CC; c++) {
                f0[c] += ex2f(d0 * k2[c]) * cf[c];
                f1[c] += ex2f(d1 * k2[c]) * cf[c];
            }
        }
    }

    #pragma unroll
    for (int c = 0; c < CC; c++) {
        s_part[w][c][lane]      = f0[c];
        s_part[w][c][lane + 32] = f1[c];
    }
    __syncthreads();

    // ---- stage 2: reduce 16 warps; thread = (c = tid>>6, mm = tid&63) ----
    {
        const int c  = tid >> 6;
        const int mm = tid & 63;
        float acc = 0.0f;
        #pragma unroll
        for (int ww = 0; ww < NWARP; ww++) acc += s_part[ww][c][mm];
        if (c == 0) s_dens[mm] = acc;
        __syncthreads();

        float tm = ti[(size_t)b * MM + mbase + mm];
        float g  = uni ? ex2f(k2u * tm * tm) : 1.0f;
        float d0 = s_dens[mm] * g;                   // true density
        float inv = g / (d0 + 1e-8f);
        s_v[c][mm] = (c == 0) ? d0 : acc * inv;
        __syncthreads();
    }

    // ---- stage 3: (8 -> 64) GEMM + bias; thread = (mm = tid>>3, og = tid&7), 8 outputs ----
    {
        const int mm = tid >> 3;
        const int og = tid & 7;
        float v[CC];
        #pragma unroll
        for (int c = 0; c < CC; c++) v[c] = s_v[c][mm];

        float4 r0 = *(const float4*)&s_bias[og * 8];
        float4 r1 = *(const float4*)&s_bias[og * 8 + 4];
        #pragma unroll
        for (int c = 0; c < CC; c++) {
            float4 w0 = *(const float4*)&s_Wt[c][og * 8];
            float4 w1 = *(const float4*)&s_Wt[c][og * 8 + 4];
            r0.x = fmaf(v[c], w0.x, r0.x);
            r0.y = fmaf(v[c], w0.y, r0.y);
            r0.z = fmaf(v[c], w0.z, r0.z);
            r0.w = fmaf(v[c], w0.w, r0.w);
            r1.x = fmaf(v[c], w1.x, r1.x);
            r1.y = fmaf(v[c], w1.y, r1.y);
            r1.z = fmaf(v[c], w1.z, r1.z);
            r1.w = fmaf(v[c], w1.w, r1.w);
        }
        float4* outp = (float4*)(out + ((size_t)(b * MM + mbase + mm)) * COUT + og * 8);
        outp[0] = r0;
        outp[1] = r1;
    }
}

extern "C" void kernel_launch(void* const* d_in, const int* in_sizes, int n_in,
                              void* d_out, int out_size) {
    const float* ci    = (const float*)d_in[0];
    const float* co    = (const float*)d_in[1];
    const float* ti    = (const float*)d_in[2];
    const float* sigma = (const float*)d_in[3];
    const float* W     = (const float*)d_in[4];
    const float* bias  = (const float*)d_in[5];
    float* out = (float*)d_out;

    dim3 grid(BB * (MM / MPB));   // 256 blocks
    dim3 block(TPB);              // 512 threads (16 warps)
    convdeepset_kernel<<<grid, block>>>(ci, co, ti, sigma, W, bias, out);
}